// round 10
// baseline (speedup 1.0000x reference)
#include <cuda_runtime.h>
#include <cstdint>

// ChebyshevEncoder: x [B=16, N=65536, D=2] fp32 -> out [B, N, D*ORDER] fp32
// out[p*60 + d*30 + m] = T_m(x[p][d]) for pair p = b*N+n.
//
// R10 = R9 (block-staged smem -> one cp.async.bulk per CTA, wait_group.READ
// exit, L2::evict_first on the bulk store) + streaming loads (__ldcs) for x.
// R9's 4.5us wall-time win came from evict_first draining the dirty output
// stream between graph replays (ncu kernel time unchanged at 40.6us);
// __ldcs extends the same no-L2-residency policy to the 8.4MB input.

#define ORDER 30
#define TPB   128
#define BYTES_PER_PAIR 240                   // 60 floats

__device__ __forceinline__ uint32_t smem_u32(const void* p) {
    uint32_t a;
    asm("{ .reg .u64 t; cvta.to.shared.u64 t, %1; cvt.u32.u64 %0, t; }"
        : "=r"(a) : "l"(p));
    return a;
}

__global__ __launch_bounds__(TPB) void cheb_kernel(
    const float2* __restrict__ x,
    float* __restrict__ out,
    int npairs)
{
    __shared__ __align__(16) float s[TPB * 60];   // 30720 B, exact output order

    const int t = threadIdx.x;
    const int blockPair = blockIdx.x * TPB;
    const int p = blockPair + t;

    if (p < npairs) {
        const float2 xv = __ldcs(&x[p]);          // streaming: read-once input

        float T[60];
        // d = 0 -> T[0..29]
        {
            const float xx = xv.x;
            const float x2 = xx + xx;
            T[0] = 1.0f;
            T[1] = xx;
#pragma unroll
            for (int m = 2; m < ORDER; m++)
                T[m] = fmaf(x2, T[m - 1], -T[m - 2]);
        }
        // d = 1 -> T[30..59]
        {
            const float xx = xv.y;
            const float x2 = xx + xx;
            T[ORDER + 0] = 1.0f;
            T[ORDER + 1] = xx;
#pragma unroll
            for (int m = 2; m < ORDER; m++)
                T[ORDER + m] = fmaf(x2, T[ORDER + m - 1], -T[ORDER + m - 2]);
        }

        // 15 STS.128 at 16B-unit addr 15*t + k: conflict-free within each
        // quarter-warp (15t mod 8 bijective over 8 consecutive lanes).
        float4* dst = reinterpret_cast<float4*>(&s[t * 60]);
        const float4* src = reinterpret_cast<const float4*>(T);
#pragma unroll
        for (int k = 0; k < 15; k++)
            dst[k] = src[k];
    }
    __syncthreads();

    if (t == 0) {
        int cnt = npairs - blockPair;
        if (cnt > TPB) cnt = TPB;
        if (cnt > 0) {
            const uint32_t sbytes = (uint32_t)cnt * BYTES_PER_PAIR;
            const uint32_t saddr  = smem_u32(s);
            float* gdst = out + (size_t)blockPair * 60;

            // Order generic-proxy STS before the async-proxy smem read.
            asm volatile("fence.proxy.async.shared::cta;" ::: "memory");
            asm volatile(
                "{\n\t"
                ".reg .b64 pol;\n\t"
                "createpolicy.fractional.L2::evict_first.b64 pol, 1.0;\n\t"
                "cp.async.bulk.global.shared::cta.bulk_group.L2::cache_hint "
                "[%0], [%1], %2, pol;\n\t"
                "}"
                :: "l"(gdst), "r"(saddr), "r"(sbytes)
                : "memory");
            asm volatile("cp.async.bulk.commit_group;" ::: "memory");
            // Exit-safe once smem has been READ; writes drain after exit.
            asm volatile("cp.async.bulk.wait_group.read 0;" ::: "memory");
        }
    }
}

extern "C" void kernel_launch(void* const* d_in, const int* in_sizes, int n_in,
                              void* d_out, int out_size)
{
    (void)n_in; (void)out_size;
    const float2* x = (const float2*)d_in[0];
    float* out = (float*)d_out;

    const int nelem  = in_sizes[0];      // B*N*D floats
    const int npairs = nelem / 2;        // B*N pairs (D=2)
    const int blocks = (npairs + TPB - 1) / TPB;

    cheb_kernel<<<blocks, TPB>>>(x, out, npairs);
}

// round 12
// speedup vs baseline: 1.1235x; 1.1235x over previous
#include <cuda_runtime.h>
#include <cstdint>

// ChebyshevEncoder: x [B=16, N=65536, D=2] fp32 -> out [B, N, D*ORDER] fp32
// out[p*60 + d*30 + m] = T_m(x[p][d]) for pair p = b*N+n.
//
// R12 = R11/R9 resubmitted byte-identical (R11 bench was an infra failure).
// Single-variable adjudication vs R10: __ldg (default, replay-resident
// input) instead of __ldcs, with L2::evict_first on the output bulk store.
//
// Structure: block-staged smem (exact output order, conflict-free STS.128)
// -> one cp.async.bulk per CTA with L2::evict_first -> wait_group.READ exit.

#define ORDER 30
#define TPB   128
#define BYTES_PER_PAIR 240                   // 60 floats

__device__ __forceinline__ uint32_t smem_u32(const void* p) {
    uint32_t a;
    asm("{ .reg .u64 t; cvta.to.shared.u64 t, %1; cvt.u32.u64 %0, t; }"
        : "=r"(a) : "l"(p));
    return a;
}

__global__ __launch_bounds__(TPB) void cheb_kernel(
    const float2* __restrict__ x,
    float* __restrict__ out,
    int npairs)
{
    __shared__ __align__(16) float s[TPB * 60];   // 30720 B, exact output order

    const int t = threadIdx.x;
    const int blockPair = blockIdx.x * TPB;
    const int p = blockPair + t;

    if (p < npairs) {
        const float2 xv = __ldg(&x[p]);           // default policy: input may
                                                  // stay L2-resident across replays

        float T[60];
        // d = 0 -> T[0..29]
        {
            const float xx = xv.x;
            const float x2 = xx + xx;
            T[0] = 1.0f;
            T[1] = xx;
#pragma unroll
            for (int m = 2; m < ORDER; m++)
                T[m] = fmaf(x2, T[m - 1], -T[m - 2]);
        }
        // d = 1 -> T[30..59]
        {
            const float xx = xv.y;
            const float x2 = xx + xx;
            T[ORDER + 0] = 1.0f;
            T[ORDER + 1] = xx;
#pragma unroll
            for (int m = 2; m < ORDER; m++)
                T[ORDER + m] = fmaf(x2, T[ORDER + m - 1], -T[ORDER + m - 2]);
        }

        // 15 STS.128 at 16B-unit addr 15*t + k: conflict-free within each
        // quarter-warp (15t mod 8 bijective over 8 consecutive lanes).
        float4* dst = reinterpret_cast<float4*>(&s[t * 60]);
        const float4* src = reinterpret_cast<const float4*>(T);
#pragma unroll
        for (int k = 0; k < 15; k++)
            dst[k] = src[k];
    }
    __syncthreads();

    if (t == 0) {
        int cnt = npairs - blockPair;
        if (cnt > TPB) cnt = TPB;
        if (cnt > 0) {
            const uint32_t sbytes = (uint32_t)cnt * BYTES_PER_PAIR;
            const uint32_t saddr  = smem_u32(s);
            float* gdst = out + (size_t)blockPair * 60;

            // Order generic-proxy STS before the async-proxy smem read.
            asm volatile("fence.proxy.async.shared::cta;" ::: "memory");
            asm volatile(
                "{\n\t"
                ".reg .b64 pol;\n\t"
                "createpolicy.fractional.L2::evict_first.b64 pol, 1.0;\n\t"
                "cp.async.bulk.global.shared::cta.bulk_group.L2::cache_hint "
                "[%0], [%1], %2, pol;\n\t"
                "}"
                :: "l"(gdst), "r"(saddr), "r"(sbytes)
                : "memory");
            asm volatile("cp.async.bulk.commit_group;" ::: "memory");
            // Exit-safe once smem has been READ; writes drain after exit.
            asm volatile("cp.async.bulk.wait_group.read 0;" ::: "memory");
        }
    }
}

extern "C" void kernel_launch(void* const* d_in, const int* in_sizes, int n_in,
                              void* d_out, int out_size)
{
    (void)n_in; (void)out_size;
    const float2* x = (const float2*)d_in[0];
    float* out = (float*)d_out;

    const int nelem  = in_sizes[0];      // B*N*D floats
    const int npairs = nelem / 2;        // B*N pairs (D=2)
    const int blocks = (npairs + TPB - 1) / TPB;

    cheb_kernel<<<blocks, TPB>>>(x, out, npairs);
}